// round 16
// baseline (speedup 1.0000x reference)
#include <cuda_runtime.h>
#include <cuda_bf16.h>
#include <cstdint>

#define D_ 512
#define S_ 2048
#define B_ 4
#define M_ (B_*S_)
#define KC_ 1024   // concat(re,im) contraction length

// ---- scratch (device globals; no allocation allowed) ----
__device__ __align__(16) float g_Vre[M_*D_];
__device__ __align__(16) float g_S[(size_t)B_*S_*S_];
__device__ __align__(16) __nv_bfloat16 g_Qhi[(size_t)M_*KC_], g_Qlo[(size_t)M_*KC_];
__device__ __align__(16) __nv_bfloat16 g_Khi[(size_t)M_*KC_], g_Klo[(size_t)M_*KC_];
__device__ __align__(16) __nv_bfloat16 g_Xhi[(size_t)M_*KC_], g_Xlo[(size_t)M_*KC_];
__device__ __align__(16) __nv_bfloat16 g_WBhi[3][(size_t)KC_*KC_], g_WBlo[3][(size_t)KC_*KC_];
__device__ __align__(16) __nv_bfloat16 g_Phi[(size_t)B_*S_*S_], g_Plo[(size_t)B_*S_*S_];
__device__ __align__(16) __nv_bfloat16 g_Vthi[(size_t)B_*D_*S_], g_Vtlo[(size_t)B_*D_*S_];

// =====================================================================
// helpers
// =====================================================================
static __device__ __forceinline__ uint32_t smem_u32(const void* p) {
    uint32_t a;
    asm("{ .reg .u64 t; cvta.to.shared.u64 t, %1; cvt.u32.u64 %0, t; }"
        : "=r"(a) : "l"(p));
    return a;
}
static __device__ __forceinline__ void ldsm_x4(uint32_t addr, uint32_t& r0,
                                               uint32_t& r1, uint32_t& r2, uint32_t& r3) {
    asm volatile("ldmatrix.sync.aligned.m8n8.x4.shared.b16 {%0,%1,%2,%3}, [%4];"
                 : "=r"(r0), "=r"(r1), "=r"(r2), "=r"(r3) : "r"(addr));
}
static __device__ __forceinline__ void mma_bf16(float* d, const uint32_t* a,
                                                const uint32_t* b) {
    asm volatile("mma.sync.aligned.m16n8k16.row.col.f32.bf16.bf16.f32 "
                 "{%0,%1,%2,%3}, {%4,%5,%6,%7}, {%8,%9}, {%0,%1,%2,%3};"
                 : "+f"(d[0]), "+f"(d[1]), "+f"(d[2]), "+f"(d[3])
                 : "r"(a[0]), "r"(a[1]), "r"(a[2]), "r"(a[3]),
                   "r"(b[0]), "r"(b[1]));
}
#define CP_ASYNC16(sa, gp) \
    asm volatile("cp.async.cg.shared.global [%0], [%1], 16;" :: "r"(sa), "l"(gp))
#define CP_COMMIT()  asm volatile("cp.async.commit_group;" ::: "memory")
#define CP_WAIT_1()  asm volatile("cp.async.wait_group 1;" ::: "memory")
#define CP_WAIT_0()  asm volatile("cp.async.wait_group 0;" ::: "memory")

static __device__ __forceinline__ void split_store4(
    __nv_bfloat16* hi, __nv_bfloat16* lo, size_t off, float4 v) {
    __nv_bfloat16 h0 = __float2bfloat16_rn(v.x), h1 = __float2bfloat16_rn(v.y);
    __nv_bfloat16 h2 = __float2bfloat16_rn(v.z), h3 = __float2bfloat16_rn(v.w);
    *(__nv_bfloat162*)(hi + off)     = __nv_bfloat162(h0, h1);
    *(__nv_bfloat162*)(hi + off + 2) = __nv_bfloat162(h2, h3);
    *(__nv_bfloat162*)(lo + off)     = __nv_bfloat162(
        __float2bfloat16_rn(v.x - __bfloat162float(h0)),
        __float2bfloat16_rn(v.y - __bfloat162float(h1)));
    *(__nv_bfloat162*)(lo + off + 2) = __nv_bfloat162(
        __float2bfloat16_rn(v.z - __bfloat162float(h2)),
        __float2bfloat16_rn(v.w - __bfloat162float(h3)));
}
static __device__ __forceinline__ void split_store2(
    __nv_bfloat16* hi, __nv_bfloat16* lo, size_t off, float v0, float v1) {
    __nv_bfloat16 h0 = __float2bfloat16_rn(v0), h1 = __float2bfloat16_rn(v1);
    *(__nv_bfloat162*)(hi + off) = __nv_bfloat162(h0, h1);
    *(__nv_bfloat162*)(lo + off) = __nv_bfloat162(
        __float2bfloat16_rn(v0 - __bfloat162float(h0)),
        __float2bfloat16_rn(v1 - __bfloat162float(h1)));
}
// Fast exp on the FMA pipe (degree-5 poly); x <= 0 expected.
static __device__ __forceinline__ float fexp(float x) {
    x = fmaxf(x, -87.0f);
    const float n = rintf(x * 1.44269504f);
    const float r = fmaf(n, -0.693359375f, x) - n * -2.12194440e-4f;
    float p = 1.9875691500e-4f;
    p = fmaf(p, r, 1.3981999507e-3f);
    p = fmaf(p, r, 8.3334519073e-3f);
    p = fmaf(p, r, 4.1665795894e-2f);
    p = fmaf(p, r, 1.6666665459e-1f);
    p = fmaf(p, r, 5.0000001201e-1f);
    p = fmaf(p * r, r, r) + 1.0f;
    const int e = ((int)n + 127) << 23;
    return p * __int_as_float(e);
}

// =====================================================================
// Fused converts
// =====================================================================
__global__ __launch_bounds__(256) void convert_all_kernel(
    const float* __restrict__ xre, const float* __restrict__ xim,
    const float* __restrict__ Wqre, const float* __restrict__ Wqim,
    const float* __restrict__ Wkre, const float* __restrict__ Wkim,
    const float* __restrict__ Wvre, const float* __restrict__ Wvim)
{
    const int bb = blockIdx.x;
    if (bb < 8192) {
        const size_t idx = (size_t)bb * 256 + threadIdx.x;
        const size_t row = idx >> 8;
        const int c4 = (int)(idx & 255) * 4;
        const size_t soff = row * D_ + ((c4 < D_) ? c4 : c4 - D_);
        const float4 v = (c4 < D_) ? *(const float4*)(xre + soff)
                                   : *(const float4*)(xim + soff);
        split_store4(g_Xhi, g_Xlo, row * KC_ + c4, v);
        return;
    }
    int w; const float *Wre, *Wim; int base;
    if (bb < 9216)       { w = 0; Wre = Wqre; Wim = Wqim; base = 8192; }
    else if (bb < 10240) { w = 1; Wre = Wkre; Wim = Wkim; base = 9216; }
    else                 { w = 2; Wre = Wvre; Wim = Wvim; base = 10240; }
    const size_t idx = (size_t)(bb - base) * 256 + threadIdx.x;
    const int n = (int)(idx >> 8);
    const int c4 = (int)(idx & 255) * 4;
    float4 v;
    if (n < D_) {
        if (c4 < D_) v = *(const float4*)(Wre + (size_t)n * D_ + c4);
        else {
            v = *(const float4*)(Wim + (size_t)n * D_ + c4 - D_);
            v.x = -v.x; v.y = -v.y; v.z = -v.z; v.w = -v.w;
        }
    } else {
        if (c4 < D_) v = *(const float4*)(Wim + (size_t)(n - D_) * D_ + c4);
        else         v = *(const float4*)(Wre + (size_t)(n - D_) * D_ + c4 - D_);
    }
    split_store4(g_WBhi[w], g_WBlo[w], (size_t)n * KC_ + c4, v);
}

__global__ void vtrans_kernel()
{
    __shared__ float sm[32][33];
    const int b = blockIdx.z;
    const int e0 = blockIdx.x * 32, t0 = blockIdx.y * 32;
    const int tx = threadIdx.x, ty = threadIdx.y;  // 32 x 8
    const float* src = g_Vre + (size_t)b * S_ * D_;
#pragma unroll
    for (int i = 0; i < 4; i++)
        sm[ty + i*8][tx] = src[(size_t)(t0 + ty + i*8) * D_ + e0 + tx];
    __syncthreads();
    const size_t dbase = (size_t)b * D_ * S_;
#pragma unroll
    for (int i = 0; i < 4; i++) {
        const int e = e0 + ty + i*8, t = t0 + tx;
        const float v = sm[tx][ty + i*8];
        const __nv_bfloat16 h = __float2bfloat16_rn(v);
        g_Vthi[dbase + (size_t)e * S_ + t] = h;
        g_Vtlo[dbase + (size_t)e * S_ + t] =
            __float2bfloat16_rn(v - __bfloat162float(h));
    }
}

// =====================================================================
// Unified mma GEMM, CTA 128x128, 4 warps (2x2), warp tile 64x64,
// cp.async 3-stage pipeline. kind 0: merged proj; 1: scores; 2: AV.
// 3-pass split-2 everywhere.
// =====================================================================
__global__ __launch_bounds__(128) void gemm_mma_kernel(
    int kind,
    const float* __restrict__ bqre, const float* __restrict__ bqim,
    const float* __restrict__ bkre, const float* __restrict__ bkim,
    const float* __restrict__ bvre,
    float* __restrict__ outp)
{
    __shared__ __align__(128) uint8_t smA[3][8192];
    __shared__ __align__(128) uint8_t smB[3][8192];

    const int tid = threadIdx.x;
    const int wid = tid >> 5, lid = tid & 31;
    const int wm = wid >> 1, wn = wid & 1;   // warp grid 2 x 2

    int mode, m0, n0, z = 0;
    if (kind == 0) {
        int t = blockIdx.x;
        if (t < 512)       { mode = 0; m0 = (t >> 3) * 128; n0 = (t & 7) * 128; }
        else if (t < 1024) { t -= 512;  mode = 1; m0 = (t >> 3) * 128; n0 = (t & 7) * 128; }
        else               { t -= 1024; mode = 2; m0 = (t >> 2) * 128; n0 = (t & 3) * 128; }
    } else if (kind == 1) {
        mode = 4; m0 = blockIdx.y * 128; n0 = blockIdx.x * 128; z = blockIdx.z;
    } else {
        mode = 3; m0 = blockIdx.y * 128; n0 = blockIdx.x * 128; z = blockIdx.z;
    }

    const __nv_bfloat16 *A0, *A1, *A2, *B0, *B1, *B2;
    int lda, Kpass;
    size_t abase = 0, bbase = 0;
    if (mode <= 2) {
        A0 = g_Xhi; A1 = g_Xlo; A2 = g_Xhi;
        B0 = g_WBhi[mode]; B1 = g_WBhi[mode]; B2 = g_WBlo[mode];
        lda = KC_; Kpass = KC_;
    } else if (mode == 3) {
        A0 = g_Phi; A1 = g_Plo; A2 = g_Phi;
        B0 = g_Vthi; B1 = g_Vthi; B2 = g_Vtlo;
        lda = S_; Kpass = S_;
        abase = (size_t)z * S_ * S_;
        bbase = (size_t)z * D_ * S_;
    } else {
        A0 = g_Qhi; A1 = g_Qlo; A2 = g_Qhi;
        B0 = g_Khi; B1 = g_Khi; B2 = g_Klo;
        lda = KC_; Kpass = KC_;
        abase = (size_t)z * S_ * KC_;
        bbase = (size_t)z * S_ * KC_;
    }
    const int KCH = Kpass / 32;
    const int NIT = 3 * KCH;

    // ---- global load mapping: thread t loads row t of A and of B (4 x 16B) ----
    const size_t aoff = abase + (size_t)(m0 + tid) * lda;
    const size_t boff = bbase + (size_t)(n0 + tid) * lda;

    uint32_t st_off[4];
    {
        const int pr = tid >> 1, h = tid & 1;
#pragma unroll
        for (int q = 0; q < 4; q++) {
            int pos = h * 4 + q;
            st_off[q] = (uint32_t)(pr * 128 + (pos ^ (pr & 7)) * 16);
        }
    }

    uint32_t offA[4][2];   // [mt][ks]
#pragma unroll
    for (int mt = 0; mt < 4; mt++)
#pragma unroll
        for (int ks = 0; ks < 2; ks++) {
            int r = wm * 64 + mt * 16 + (lid & 15);
            int c16 = ks * 2 + (lid >> 4);
            int pr = r >> 1, hh = r & 1;
            int pos = hh * 4 + c16;
            offA[mt][ks] = (uint32_t)(pr * 128 + (pos ^ (pr & 7)) * 16);
        }
    uint32_t offB[4][2];   // [ntp][ks]
#pragma unroll
    for (int ntp = 0; ntp < 4; ntp++)
#pragma unroll
        for (int ks = 0; ks < 2; ks++) {
            int rn = wn * 64 + ntp * 16 + (lid & 7) + ((lid >> 4) & 1) * 8;
            int c16 = ks * 2 + ((lid >> 3) & 1);
            int pr = rn >> 1, hh = rn & 1;
            int pos = hh * 4 + c16;
            offB[ntp][ks] = (uint32_t)(pr * 128 + (pos ^ (pr & 7)) * 16);
        }

    float acc[4][8][4];
#pragma unroll
    for (int mt = 0; mt < 4; mt++)
#pragma unroll
        for (int nt = 0; nt < 8; nt++)
#pragma unroll
            for (int i = 0; i < 4; i++) acc[mt][nt][i] = 0.f;

    uint32_t aS[3], bS[3];
#pragma unroll
    for (int s = 0; s < 3; s++) {
        aS[s] = smem_u32(&smA[s][0]);
        bS[s] = smem_u32(&smB[s][0]);
    }

    auto issue = [&](int cc, int s) {
        const int pp = cc / KCH;
        const int kk = (cc - pp * KCH) * 32;
        const __nv_bfloat16* A  = (pp == 0) ? A0 : (pp == 1) ? A1 : A2;
        const __nv_bfloat16* Bq = (pp == 0) ? B0 : (pp == 1) ? B1 : B2;
#pragma unroll
        for (int q = 0; q < 4; q++) {
            CP_ASYNC16(aS[s] + st_off[q], A  + aoff + kk + q * 8);
            CP_ASYNC16(bS[s] + st_off[q], Bq + boff + kk + q * 8);
        }
    };

    issue(0, 0); CP_COMMIT();
    issue(1, 1); CP_COMMIT();

    int stage = 0;
    for (int c = 0; c < NIT; c++) {
        if (c + 1 < NIT) { CP_WAIT_1(); } else { CP_WAIT_0(); }
        __syncthreads();
        if (c + 2 < NIT) {
            int s2 = stage + 2; if (s2 >= 3) s2 -= 3;
            issue(c + 2, s2);
            CP_COMMIT();
        }
        const uint32_t aBase = aS[stage];
        const uint32_t bBase = bS[stage];
#pragma unroll
        for (int ks = 0; ks < 2; ks++) {
            uint32_t af[4][4];
#pragma unroll
            for (int mt = 0; mt < 4; mt++)
                ldsm_x4(aBase + offA[mt][ks], af[mt][0], af[mt][1], af[mt][2], af[mt][3]);
            uint32_t bf[8][2];
#pragma unroll
            for (int ntp = 0; ntp < 4; ntp++)
                ldsm_x4(bBase + offB[ntp][ks],
                        bf[2*ntp][0], bf[2*ntp][1], bf[2*ntp+1][0], bf[2*ntp+1][1]);
#pragma unroll
            for (int mt = 0; mt < 4; mt++)
#pragma unroll
                for (int nt = 0; nt < 8; nt++)
                    mma_bf16(acc[mt][nt], af[mt], bf[nt]);
        }
        if (++stage == 3) stage = 0;
    }

    // ---- epilogue ----
    if (mode <= 1) {
        __nv_bfloat16* ph = (mode == 0) ? g_Qhi : g_Khi;
        __nv_bfloat16* pl = (mode == 0) ? g_Qlo : g_Klo;
        const float* bre = (mode == 0) ? bqre : bkre;
        const float* bim = (mode == 0) ? bqim : bkim;
#pragma unroll
        for (int mt = 0; mt < 4; mt++) {
            const int row = m0 + wm * 64 + mt * 16 + (lid >> 2);
#pragma unroll
            for (int nt = 0; nt < 8; nt++) {
                const int col = n0 + wn * 64 + nt * 8 + (lid & 3) * 2;
                const float b0 = (col < D_) ? bre[col]     : bim[col - D_];
                const float b1 = (col < D_) ? bre[col + 1] : bim[col - D_ + 1];
                split_store2(ph, pl, (size_t)row * KC_ + col,
                             acc[mt][nt][0] + b0, acc[mt][nt][1] + b1);
                split_store2(ph, pl, (size_t)(row + 8) * KC_ + col,
                             acc[mt][nt][2] + b0, acc[mt][nt][3] + b1);
            }
        }
    } else if (mode == 2) {
#pragma unroll
        for (int mt = 0; mt < 4; mt++) {
            const int row = m0 + wm * 64 + mt * 16 + (lid >> 2);
#pragma unroll
            for (int nt = 0; nt < 8; nt++) {
                const int col = n0 + wn * 64 + nt * 8 + (lid & 3) * 2;
                const float b0 = bvre[col], b1 = bvre[col + 1];
                *(float2*)(g_Vre + (size_t)row * D_ + col) =
                    make_float2(acc[mt][nt][0] + b0, acc[mt][nt][1] + b1);
                *(float2*)(g_Vre + (size_t)(row + 8) * D_ + col) =
                    make_float2(acc[mt][nt][2] + b0, acc[mt][nt][3] + b1);
            }
        }
    } else if (mode == 3) {
#pragma unroll
        for (int mt = 0; mt < 4; mt++) {
            const int row = m0 + wm * 64 + mt * 16 + (lid >> 2);
            float* o = outp + ((size_t)z * S_ + row) * D_;
#pragma unroll
            for (int nt = 0; nt < 8; nt++) {
                const int col = n0 + wn * 64 + nt * 8 + (lid & 3) * 2;
                *(float2*)(o + col)          = make_float2(acc[mt][nt][0], acc[mt][nt][1]);
                *(float2*)(o + 8 * D_ + col) = make_float2(acc[mt][nt][2], acc[mt][nt][3]);
            }
        }
    } else {
#pragma unroll
        for (int mt = 0; mt < 4; mt++) {
            const int row = m0 + wm * 64 + mt * 16 + (lid >> 2);
            float* Sr = g_S + ((size_t)z * S_ + row) * S_;
#pragma unroll
            for (int nt = 0; nt < 8; nt++) {
                const int col = n0 + wn * 64 + nt * 8 + (lid & 3) * 2;
                *(float2*)(Sr + col)          = make_float2(acc[mt][nt][0], acc[mt][nt][1]);
                *(float2*)(Sr + 8 * S_ + col) = make_float2(acc[mt][nt][2], acc[mt][nt][3]);
            }
        }
    }
}

// =====================================================================
// Row softmax; poly exp (FMA pipe); writes split-bf16 P.
// =====================================================================
__global__ __launch_bounds__(256) void softmax_kernel()
{
    __shared__ float sh[8];
    const size_t row = blockIdx.x;
    const float* p = g_S + row * S_;
    const int t = threadIdx.x;

    float4 v0 = *(const float4*)(p + t*4);
    float4 v1 = *(const float4*)(p + 1024 + t*4);

    float m = fmaxf(fmaxf(fmaxf(v0.x, v0.y), fmaxf(v0.z, v0.w)),
                    fmaxf(fmaxf(v1.x, v1.y), fmaxf(v1.z, v1.w)));
#pragma unroll
    for (int o = 16; o; o >>= 1) m = fmaxf(m, __shfl_xor_sync(0xffffffffu, m, o));
    if ((t & 31) == 0) sh[t >> 5] = m;
    __syncthreads();
    m = sh[0];
#pragma unroll
    for (int i = 1; i < 8; i++) m = fmaxf(m, sh[i]);
    __syncthreads();

    v0.x = fexp(v0.x - m); v0.y = fexp(v0.y - m);
    v0.z = fexp(v0.z - m); v0.w = fexp(v0.w - m);
    v1.x = fexp(v1.x - m); v1.y = fexp(v1.y - m);
    v1.z = fexp(v1.z - m); v1.w = fexp(v1.w - m);

    float s = (v0.x + v0.y) + (v0.z + v0.w) + (v1.x + v1.y) + (v1.z + v1.w);
#pragma unroll
    for (int o = 16; o; o >>= 1) s += __shfl_xor_sync(0xffffffffu, s, o);
    if ((t & 31) == 0) sh[t >> 5] = s;
    __syncthreads();
    s = (sh[0] + sh[1]) + (sh[2] + sh[3]) + (sh[4] + sh[5]) + (sh[6] + sh[7]);
    const float inv = 1.0f / s;

    v0.x *= inv; v0.y *= inv; v0.z *= inv; v0.w *= inv;
    v1.x *= inv; v1.y *= inv; v1.z *= inv; v1.w *= inv;
    split_store4(g_Phi, g_Plo, row * S_ + t*4, v0);
    split_store4(g_Phi, g_Plo, row * S_ + 1024 + t*4, v1);
}

// =====================================================================
extern "C" void kernel_launch(void* const* d_in, const int* in_sizes, int n_in,
                              void* d_out, int out_size)
{
    (void)in_sizes; (void)n_in; (void)out_size;

    const float* xre   = (const float*)d_in[0];
    const float* xim   = (const float*)d_in[1];
    const float* Wq_re = (const float*)d_in[2];
    const float* Wq_im = (const float*)d_in[3];
    const float* bq_re = (const float*)d_in[4];
    const float* bq_im = (const float*)d_in[5];
    const float* Wk_re = (const float*)d_in[6];
    const float* Wk_im = (const float*)d_in[7];
    const float* bk_re = (const float*)d_in[8];
    const float* bk_im = (const float*)d_in[9];
    const float* Wv_re = (const float*)d_in[10];
    const float* Wv_im = (const float*)d_in[11];
    const float* bv_re = (const float*)d_in[12];

    convert_all_kernel<<<10752, 256>>>(xre, xim, Wq_re, Wq_im,
                                       Wk_re, Wk_im, Wv_re, Wv_im);

    // merged Q/K/V projections: 512 + 512 + 256 tiles
    gemm_mma_kernel<<<1280, 128>>>(0, bq_re, bq_im, bk_re, bk_im, bv_re, nullptr);

    vtrans_kernel<<<dim3(D_/32, S_/32, B_), dim3(32, 8)>>>();

    // scores: (16,16,4)
    gemm_mma_kernel<<<dim3(S_/128, S_/128, B_), 128>>>(
        1, nullptr, nullptr, nullptr, nullptr, nullptr, nullptr);

    softmax_kernel<<<B_*S_, 256>>>();

    // AV: (4,16,4)
    gemm_mma_kernel<<<dim3(D_/128, S_/128, B_), 128>>>(
        2, nullptr, nullptr, nullptr, nullptr, nullptr, (float*)d_out);
}

// round 17
// speedup vs baseline: 1.5879x; 1.5879x over previous
#include <cuda_runtime.h>
#include <cuda_bf16.h>
#include <cstdint>

#define D_ 512
#define S_ 2048
#define B_ 4
#define M_ (B_*S_)
#define KC_ 1024   // concat(re,im) contraction length

// ---- scratch (device globals; no allocation allowed) ----
__device__ __align__(16) float g_Vre[M_*D_];
__device__ __align__(16) float g_S[(size_t)B_*S_*S_];
__device__ __align__(16) __nv_bfloat16 g_Qhi[(size_t)M_*KC_], g_Qlo[(size_t)M_*KC_];
__device__ __align__(16) __nv_bfloat16 g_Khi[(size_t)M_*KC_], g_Klo[(size_t)M_*KC_];
__device__ __align__(16) __nv_bfloat16 g_Xhi[(size_t)M_*KC_], g_Xlo[(size_t)M_*KC_];
__device__ __align__(16) __nv_bfloat16 g_WBhi[3][(size_t)KC_*KC_], g_WBlo[3][(size_t)KC_*KC_];
__device__ __align__(16) __nv_bfloat16 g_Phi[(size_t)B_*S_*S_], g_Plo[(size_t)B_*S_*S_];
__device__ __align__(16) __nv_bfloat16 g_Vthi[(size_t)B_*D_*S_], g_Vtlo[(size_t)B_*D_*S_];

// =====================================================================
// helpers
// =====================================================================
static __device__ __forceinline__ uint32_t smem_u32(const void* p) {
    uint32_t a;
    asm("{ .reg .u64 t; cvta.to.shared.u64 t, %1; cvt.u32.u64 %0, t; }"
        : "=r"(a) : "l"(p));
    return a;
}
static __device__ __forceinline__ void ldsm_x4(uint32_t addr, uint32_t& r0,
                                               uint32_t& r1, uint32_t& r2, uint32_t& r3) {
    asm volatile("ldmatrix.sync.aligned.m8n8.x4.shared.b16 {%0,%1,%2,%3}, [%4];"
                 : "=r"(r0), "=r"(r1), "=r"(r2), "=r"(r3) : "r"(addr));
}
static __device__ __forceinline__ void mma_bf16(float* d, const uint32_t* a,
                                                const uint32_t* b) {
    asm volatile("mma.sync.aligned.m16n8k16.row.col.f32.bf16.bf16.f32 "
                 "{%0,%1,%2,%3}, {%4,%5,%6,%7}, {%8,%9}, {%0,%1,%2,%3};"
                 : "+f"(d[0]), "+f"(d[1]), "+f"(d[2]), "+f"(d[3])
                 : "r"(a[0]), "r"(a[1]), "r"(a[2]), "r"(a[3]),
                   "r"(b[0]), "r"(b[1]));
}
#define CP_ASYNC16(sa, gp) \
    asm volatile("cp.async.cg.shared.global [%0], [%1], 16;" :: "r"(sa), "l"(gp))
#define CP_COMMIT()  asm volatile("cp.async.commit_group;" ::: "memory")
#define CP_WAIT_1()  asm volatile("cp.async.wait_group 1;" ::: "memory")
#define CP_WAIT_0()  asm volatile("cp.async.wait_group 0;" ::: "memory")

static __device__ __forceinline__ void split_store4(
    __nv_bfloat16* hi, __nv_bfloat16* lo, size_t off, float4 v) {
    __nv_bfloat16 h0 = __float2bfloat16_rn(v.x), h1 = __float2bfloat16_rn(v.y);
    __nv_bfloat16 h2 = __float2bfloat16_rn(v.z), h3 = __float2bfloat16_rn(v.w);
    *(__nv_bfloat162*)(hi + off)     = __nv_bfloat162(h0, h1);
    *(__nv_bfloat162*)(hi + off + 2) = __nv_bfloat162(h2, h3);
    *(__nv_bfloat162*)(lo + off)     = __nv_bfloat162(
        __float2bfloat16_rn(v.x - __bfloat162float(h0)),
        __float2bfloat16_rn(v.y - __bfloat162float(h1)));
    *(__nv_bfloat162*)(lo + off + 2) = __nv_bfloat162(
        __float2bfloat16_rn(v.z - __bfloat162float(h2)),
        __float2bfloat16_rn(v.w - __bfloat162float(h3)));
}
static __device__ __forceinline__ void split_store2(
    __nv_bfloat16* hi, __nv_bfloat16* lo, size_t off, float v0, float v1) {
    __nv_bfloat16 h0 = __float2bfloat16_rn(v0), h1 = __float2bfloat16_rn(v1);
    *(__nv_bfloat162*)(hi + off) = __nv_bfloat162(h0, h1);
    *(__nv_bfloat162*)(lo + off) = __nv_bfloat162(
        __float2bfloat16_rn(v0 - __bfloat162float(h0)),
        __float2bfloat16_rn(v1 - __bfloat162float(h1)));
}
// Fast exp on the FMA pipe (degree-5 poly); x <= 0 expected.
static __device__ __forceinline__ float fexp(float x) {
    x = fmaxf(x, -87.0f);
    const float n = rintf(x * 1.44269504f);
    const float r = fmaf(n, -0.693359375f, x) - n * -2.12194440e-4f;
    float p = 1.9875691500e-4f;
    p = fmaf(p, r, 1.3981999507e-3f);
    p = fmaf(p, r, 8.3334519073e-3f);
    p = fmaf(p, r, 4.1665795894e-2f);
    p = fmaf(p, r, 1.6666665459e-1f);
    p = fmaf(p, r, 5.0000001201e-1f);
    p = fmaf(p * r, r, r) + 1.0f;
    const int e = ((int)n + 127) << 23;
    return p * __int_as_float(e);
}

// =====================================================================
// Fused converts
// =====================================================================
__global__ __launch_bounds__(256) void convert_all_kernel(
    const float* __restrict__ xre, const float* __restrict__ xim,
    const float* __restrict__ Wqre, const float* __restrict__ Wqim,
    const float* __restrict__ Wkre, const float* __restrict__ Wkim,
    const float* __restrict__ Wvre, const float* __restrict__ Wvim)
{
    const int bb = blockIdx.x;
    if (bb < 8192) {
        const size_t idx = (size_t)bb * 256 + threadIdx.x;
        const size_t row = idx >> 8;
        const int c4 = (int)(idx & 255) * 4;
        const size_t soff = row * D_ + ((c4 < D_) ? c4 : c4 - D_);
        const float4 v = (c4 < D_) ? *(const float4*)(xre + soff)
                                   : *(const float4*)(xim + soff);
        split_store4(g_Xhi, g_Xlo, row * KC_ + c4, v);
        return;
    }
    int w; const float *Wre, *Wim; int base;
    if (bb < 9216)       { w = 0; Wre = Wqre; Wim = Wqim; base = 8192; }
    else if (bb < 10240) { w = 1; Wre = Wkre; Wim = Wkim; base = 9216; }
    else                 { w = 2; Wre = Wvre; Wim = Wvim; base = 10240; }
    const size_t idx = (size_t)(bb - base) * 256 + threadIdx.x;
    const int n = (int)(idx >> 8);
    const int c4 = (int)(idx & 255) * 4;
    float4 v;
    if (n < D_) {
        if (c4 < D_) v = *(const float4*)(Wre + (size_t)n * D_ + c4);
        else {
            v = *(const float4*)(Wim + (size_t)n * D_ + c4 - D_);
            v.x = -v.x; v.y = -v.y; v.z = -v.z; v.w = -v.w;
        }
    } else {
        if (c4 < D_) v = *(const float4*)(Wim + (size_t)(n - D_) * D_ + c4);
        else         v = *(const float4*)(Wre + (size_t)(n - D_) * D_ + c4 - D_);
    }
    split_store4(g_WBhi[w], g_WBlo[w], (size_t)n * KC_ + c4, v);
}

__global__ void vtrans_kernel()
{
    __shared__ float sm[32][33];
    const int b = blockIdx.z;
    const int e0 = blockIdx.x * 32, t0 = blockIdx.y * 32;
    const int tx = threadIdx.x, ty = threadIdx.y;  // 32 x 8
    const float* src = g_Vre + (size_t)b * S_ * D_;
#pragma unroll
    for (int i = 0; i < 4; i++)
        sm[ty + i*8][tx] = src[(size_t)(t0 + ty + i*8) * D_ + e0 + tx];
    __syncthreads();
    const size_t dbase = (size_t)b * D_ * S_;
#pragma unroll
    for (int i = 0; i < 4; i++) {
        const int e = e0 + ty + i*8, t = t0 + tx;
        const float v = sm[tx][ty + i*8];
        const __nv_bfloat16 h = __float2bfloat16_rn(v);
        g_Vthi[dbase + (size_t)e * S_ + t] = h;
        g_Vtlo[dbase + (size_t)e * S_ + t] =
            __float2bfloat16_rn(v - __bfloat162float(h));
    }
}

// =====================================================================
// Unified mma GEMM, CTA 128x128, 8 warps (4x2), warp tile 32x64,
// BK=64, cp.async 3-stage pipeline (dynamic smem 96KB).
// kind 0: merged proj; 1: scores; 2: AV. 3-pass split-2.
// Smem per stage: 128 rows x 128B (one 64-elem K-chunk), SW128 swizzle.
// =====================================================================
#define STAGE_BYTES 16384
#define A_STAGES_OFF 0
#define B_STAGES_OFF (3 * STAGE_BYTES)
#define DYN_SMEM (6 * STAGE_BYTES)

__global__ __launch_bounds__(256) void gemm_mma_kernel(
    int kind,
    const float* __restrict__ bqre, const float* __restrict__ bqim,
    const float* __restrict__ bkre, const float* __restrict__ bkim,
    const float* __restrict__ bvre,
    float* __restrict__ outp)
{
    extern __shared__ __align__(128) uint8_t dynsm[];

    const int tid = threadIdx.x;
    const int wid = tid >> 5, lid = tid & 31;
    const int wm = wid >> 1, wn = wid & 1;   // warp grid 4 x 2

    int mode, m0, n0, z = 0;
    if (kind == 0) {
        int t = blockIdx.x;
        if (t < 512)       { mode = 0; m0 = (t >> 3) * 128; n0 = (t & 7) * 128; }
        else if (t < 1024) { t -= 512;  mode = 1; m0 = (t >> 3) * 128; n0 = (t & 7) * 128; }
        else               { t -= 1024; mode = 2; m0 = (t >> 2) * 128; n0 = (t & 3) * 128; }
    } else if (kind == 1) {
        mode = 4; m0 = blockIdx.y * 128; n0 = blockIdx.x * 128; z = blockIdx.z;
    } else {
        mode = 3; m0 = blockIdx.y * 128; n0 = blockIdx.x * 128; z = blockIdx.z;
    }

    const __nv_bfloat16 *A0, *A1, *A2, *B0, *B1, *B2;
    int lda, Kpass;
    size_t abase = 0, bbase = 0;
    if (mode <= 2) {
        A0 = g_Xhi; A1 = g_Xlo; A2 = g_Xhi;
        B0 = g_WBhi[mode]; B1 = g_WBhi[mode]; B2 = g_WBlo[mode];
        lda = KC_; Kpass = KC_;
    } else if (mode == 3) {
        A0 = g_Phi; A1 = g_Plo; A2 = g_Phi;
        B0 = g_Vthi; B1 = g_Vthi; B2 = g_Vtlo;
        lda = S_; Kpass = S_;
        abase = (size_t)z * S_ * S_;
        bbase = (size_t)z * D_ * S_;
    } else {
        A0 = g_Qhi; A1 = g_Qlo; A2 = g_Qhi;
        B0 = g_Khi; B1 = g_Khi; B2 = g_Klo;
        lda = KC_; Kpass = KC_;
        abase = (size_t)z * S_ * KC_;
        bbase = (size_t)z * S_ * KC_;
    }
    const int KCH = Kpass / 64;       // 64-elem chunks per pass
    const int NIT = 3 * KCH;

    // ---- global load mapping: thread t loads row t>>1, 4 x 16B (half-row) ----
    const int grow = tid >> 1;
    const int gc0  = (tid & 1) * 4;    // c16 base: 0 or 4
    const size_t aoff = abase + (size_t)(m0 + grow) * lda;
    const size_t boff = bbase + (size_t)(n0 + grow) * lda;

    uint32_t st_off[4];
#pragma unroll
    for (int q = 0; q < 4; q++) {
        int c16 = gc0 + q;
        st_off[q] = (uint32_t)(grow * 128 + ((c16 ^ (grow & 7)) * 16));
    }

    // ---- ldmatrix source offsets: [frag][ks] for ks = 0..3 ----
    uint32_t offA[2][4];
#pragma unroll
    for (int mt = 0; mt < 2; mt++)
#pragma unroll
        for (int ks = 0; ks < 4; ks++) {
            int r = wm * 32 + mt * 16 + (lid & 15);
            int c16 = ks * 2 + (lid >> 4);
            offA[mt][ks] = (uint32_t)(r * 128 + ((c16 ^ (r & 7)) * 16));
        }
    uint32_t offB[4][4];
#pragma unroll
    for (int ntp = 0; ntp < 4; ntp++)
#pragma unroll
        for (int ks = 0; ks < 4; ks++) {
            int rn = wn * 64 + ntp * 16 + (lid & 7) + ((lid >> 4) & 1) * 8;
            int c16 = ks * 2 + ((lid >> 3) & 1);
            offB[ntp][ks] = (uint32_t)(rn * 128 + ((c16 ^ (rn & 7)) * 16));
        }

    float acc[2][8][4];
#pragma unroll
    for (int mt = 0; mt < 2; mt++)
#pragma unroll
        for (int nt = 0; nt < 8; nt++)
#pragma unroll
            for (int i = 0; i < 4; i++) acc[mt][nt][i] = 0.f;

    uint32_t aS[3], bS[3];
#pragma unroll
    for (int s = 0; s < 3; s++) {
        aS[s] = smem_u32(dynsm + A_STAGES_OFF + s * STAGE_BYTES);
        bS[s] = smem_u32(dynsm + B_STAGES_OFF + s * STAGE_BYTES);
    }

    auto issue = [&](int cc, int s) {
        const int pp = cc / KCH;
        const int kk = (cc - pp * KCH) * 64;
        const __nv_bfloat16* A  = (pp == 0) ? A0 : (pp == 1) ? A1 : A2;
        const __nv_bfloat16* Bq = (pp == 0) ? B0 : (pp == 1) ? B1 : B2;
#pragma unroll
        for (int q = 0; q < 4; q++) {
            CP_ASYNC16(aS[s] + st_off[q], A  + aoff + kk + (gc0 + q) * 8);
            CP_ASYNC16(bS[s] + st_off[q], Bq + boff + kk + (gc0 + q) * 8);
        }
    };

    issue(0, 0); CP_COMMIT();
    issue(1, 1); CP_COMMIT();

    int stage = 0;
    for (int c = 0; c < NIT; c++) {
        if (c + 1 < NIT) { CP_WAIT_1(); } else { CP_WAIT_0(); }
        __syncthreads();
        if (c + 2 < NIT) {
            int s2 = stage + 2; if (s2 >= 3) s2 -= 3;
            issue(c + 2, s2);
            CP_COMMIT();
        }
        const uint32_t aBase = aS[stage];
        const uint32_t bBase = bS[stage];
#pragma unroll
        for (int ks = 0; ks < 4; ks++) {
            uint32_t af[2][4];
            ldsm_x4(aBase + offA[0][ks], af[0][0], af[0][1], af[0][2], af[0][3]);
            ldsm_x4(aBase + offA[1][ks], af[1][0], af[1][1], af[1][2], af[1][3]);
            uint32_t bf[8][2];
#pragma unroll
            for (int ntp = 0; ntp < 4; ntp++)
                ldsm_x4(bBase + offB[ntp][ks],
                        bf[2*ntp][0], bf[2*ntp][1], bf[2*ntp+1][0], bf[2*ntp+1][1]);
#pragma unroll
            for (int mt = 0; mt < 2; mt++)
#pragma unroll
                for (int nt = 0; nt < 8; nt++)
                    mma_bf16(acc[mt][nt], af[mt], bf[nt]);
        }
        if (++stage == 3) stage = 0;
    }

    // ---- epilogue ----
    if (mode <= 1) {
        __nv_bfloat16* ph = (mode == 0) ? g_Qhi : g_Khi;
        __nv_bfloat16* pl = (mode == 0) ? g_Qlo : g_Klo;
        const float* bre = (mode == 0) ? bqre : bkre;
        const float* bim = (mode == 0) ? bqim : bkim;
#pragma unroll
        for (int mt = 0; mt < 2; mt++) {
            const int row = m0 + wm * 32 + mt * 16 + (lid >> 2);
#pragma unroll
            for (int nt = 0; nt < 8; nt++) {
                const int col = n0 + wn * 64 + nt * 8 + (lid & 3) * 2;
                const float b0 = (col < D_) ? bre[col]     : bim[col - D_];
                const float b1 = (col < D_) ? bre[col + 1] : bim[col - D_ + 1];
                split_store2(ph, pl, (size_t)row * KC_ + col,
                             acc[mt][nt][0] + b0, acc[mt][nt][1] + b1);
                split_store2(ph, pl, (size_t)(row + 8) * KC_ + col,
                             acc[mt][nt][2] + b0, acc[mt][nt][3] + b1);
            }
        }
    } else if (mode == 2) {
#pragma unroll
        for (int mt = 0; mt < 2; mt++) {
            const int row = m0 + wm * 32 + mt * 16 + (lid >> 2);
#pragma unroll
            for (int nt = 0; nt < 8; nt++) {
                const int col = n0 + wn * 64 + nt * 8 + (lid & 3) * 2;
                const float b0 = bvre[col], b1 = bvre[col + 1];
                *(float2*)(g_Vre + (size_t)row * D_ + col) =
                    make_float2(acc[mt][nt][0] + b0, acc[mt][nt][1] + b1);
                *(float2*)(g_Vre + (size_t)(row + 8) * D_ + col) =
                    make_float2(acc[mt][nt][2] + b0, acc[mt][nt][3] + b1);
            }
        }
    } else if (mode == 3) {
#pragma unroll
        for (int mt = 0; mt < 2; mt++) {
            const int row = m0 + wm * 32 + mt * 16 + (lid >> 2);
            float* o = outp + ((size_t)z * S_ + row) * D_;
#pragma unroll
            for (int nt = 0; nt < 8; nt++) {
                const int col = n0 + wn * 64 + nt * 8 + (lid & 3) * 2;
                *(float2*)(o + col)          = make_float2(acc[mt][nt][0], acc[mt][nt][1]);
                *(float2*)(o + 8 * D_ + col) = make_float2(acc[mt][nt][2], acc[mt][nt][3]);
            }
        }
    } else {
#pragma unroll
        for (int mt = 0; mt < 2; mt++) {
            const int row = m0 + wm * 32 + mt * 16 + (lid >> 2);
            float* Sr = g_S + ((size_t)z * S_ + row) * S_;
#pragma unroll
            for (int nt = 0; nt < 8; nt++) {
                const int col = n0 + wn * 64 + nt * 8 + (lid & 3) * 2;
                *(float2*)(Sr + col)          = make_float2(acc[mt][nt][0], acc[mt][nt][1]);
                *(float2*)(Sr + 8 * S_ + col) = make_float2(acc[mt][nt][2], acc[mt][nt][3]);
            }
        }
    }
}

// =====================================================================
// Row softmax; poly exp (FMA pipe); writes split-bf16 P.
// =====================================================================
__global__ __launch_bounds__(256) void softmax_kernel()
{
    __shared__ float sh[8];
    const size_t row = blockIdx.x;
    const float* p = g_S + row * S_;
    const int t = threadIdx.x;

    float4 v0 = *(const float4*)(p + t*4);
    float4 v1 = *(const float4*)(p + 1024 + t*4);

    float m = fmaxf(fmaxf(fmaxf(v0.x, v0.y), fmaxf(v0.z, v0.w)),
                    fmaxf(fmaxf(v1.x, v1.y), fmaxf(v1.z, v1.w)));
#pragma unroll
    for (int o = 16; o; o >>= 1) m = fmaxf(m, __shfl_xor_sync(0xffffffffu, m, o));
    if ((t & 31) == 0) sh[t >> 5] = m;
    __syncthreads();
    m = sh[0];
#pragma unroll
    for (int i = 1; i < 8; i++) m = fmaxf(m, sh[i]);
    __syncthreads();

    v0.x = fexp(v0.x - m); v0.y = fexp(v0.y - m);
    v0.z = fexp(v0.z - m); v0.w = fexp(v0.w - m);
    v1.x = fexp(v1.x - m); v1.y = fexp(v1.y - m);
    v1.z = fexp(v1.z - m); v1.w = fexp(v1.w - m);

    float s = (v0.x + v0.y) + (v0.z + v0.w) + (v1.x + v1.y) + (v1.z + v1.w);
#pragma unroll
    for (int o = 16; o; o >>= 1) s += __shfl_xor_sync(0xffffffffu, s, o);
    if ((t & 31) == 0) sh[t >> 5] = s;
    __syncthreads();
    s = (sh[0] + sh[1]) + (sh[2] + sh[3]) + (sh[4] + sh[5]) + (sh[6] + sh[7]);
    const float inv = 1.0f / s;

    v0.x *= inv; v0.y *= inv; v0.z *= inv; v0.w *= inv;
    v1.x *= inv; v1.y *= inv; v1.z *= inv; v1.w *= inv;
    split_store4(g_Phi, g_Plo, row * S_ + t*4, v0);
    split_store4(g_Phi, g_Plo, row * S_ + 1024 + t*4, v1);
}

// =====================================================================
extern "C" void kernel_launch(void* const* d_in, const int* in_sizes, int n_in,
                              void* d_out, int out_size)
{
    (void)in_sizes; (void)n_in; (void)out_size;

    const float* xre   = (const float*)d_in[0];
    const float* xim   = (const float*)d_in[1];
    const float* Wq_re = (const float*)d_in[2];
    const float* Wq_im = (const float*)d_in[3];
    const float* bq_re = (const float*)d_in[4];
    const float* bq_im = (const float*)d_in[5];
    const float* Wk_re = (const float*)d_in[6];
    const float* Wk_im = (const float*)d_in[7];
    const float* bk_re = (const float*)d_in[8];
    const float* bk_im = (const float*)d_in[9];
    const float* Wv_re = (const float*)d_in[10];
    const float* Wv_im = (const float*)d_in[11];
    const float* bv_re = (const float*)d_in[12];

    static bool attr_set = false;
    if (!attr_set) {
        cudaFuncSetAttribute(gemm_mma_kernel,
                             cudaFuncAttributeMaxDynamicSharedMemorySize, DYN_SMEM);
        attr_set = true;
    }

    convert_all_kernel<<<10752, 256>>>(xre, xim, Wq_re, Wq_im,
                                       Wk_re, Wk_im, Wv_re, Wv_im);

    // merged Q/K/V projections: 512 + 512 + 256 tiles
    gemm_mma_kernel<<<1280, 256, DYN_SMEM>>>(0, bq_re, bq_im, bk_re, bk_im,
                                             bv_re, nullptr);

    vtrans_kernel<<<dim3(D_/32, S_/32, B_), dim3(32, 8)>>>();

    // scores: (16,16,4)
    gemm_mma_kernel<<<dim3(S_/128, S_/128, B_), 256, DYN_SMEM>>>(
        1, nullptr, nullptr, nullptr, nullptr, nullptr, nullptr);

    softmax_kernel<<<B_*S_, 256>>>();

    // AV: (4,16,4)
    gemm_mma_kernel<<<dim3(D_/128, S_/128, B_), 256, DYN_SMEM>>>(
        2, nullptr, nullptr, nullptr, nullptr, nullptr, (float*)d_out);
}